// round 12
// baseline (speedup 1.0000x reference)
#include <cuda_runtime.h>

// TT-embedding — single persistent kernel.
//   core0: (1,8,40,16)    A[x][p][b]     idx = x*640 + p*16 + b
//   core1: (16,8,32,16)   M[b][y][q][c]  idx = b*4096 + y*512 + q*16 + c
//   core2: (16,16,25,1)   C[c][z][r]     idx = c*400 + z*25 + r
//   id -> p = id/800, q = (id%800)/25, r = id%25
//   out[tok][xy*16+z] = sum_c s[pq][c][xy] * c2t[r][c][z]
//
// Phase A: build permuted s rows g_s[pq][c][a*8+m] (a=xy&7, m=xy>>3) and a
//   DUPLICATED c2t in smem: CsD[r][c][z] = {v,v} pairs (51.2 KB) so that
//   LDS.128 yields ready-made f32x2 broadcast operands (no SASS MOVs).
// Grid barrier: epoch-ticket atomic (monotonic -> graph-replay safe).
// Phase B: gather, 1 token/warp/iter; accumulators are m-PAIRS (s float4
//   halves are valid 64-bit FMA2 operands as loaded), z broadcast from CsD.
//   Inner loop per c: 2 LDG.128 + 2 LDS.128 + 16 FFMA2, zero MOVs.
//
// GRID=444 = 148 SMs x 3; __launch_bounds__(256,3): regs<=85,
// smem ~60KB x 3 = 180KB <= 228KB -> co-resident, barrier cannot deadlock.

#define NTOK   16384
#define GRID   444
#define NROWS  1280
typedef unsigned long long ull;

__device__ float g_s[NROWS * 1024];
__device__ unsigned g_bar;   // monotonic epoch counter (never reset)

__global__ __launch_bounds__(256, 3) void tt_fused(const float* __restrict__ c0,
                                                   const float* __restrict__ c1,
                                                   const float* __restrict__ c2,
                                                   const int* __restrict__ ids,
                                                   float* __restrict__ out) {
    __shared__ __align__(16) float CsD[12800];  // dup c2t: [r][c][z] -> {v,v}
    __shared__ float sA[128];                   // [x][b]
    __shared__ float sM[2048];                  // [b][y][c]
    __shared__ int sIds64;

    int t = threadIdx.x;
    int bid = blockIdx.x;

    // ---- Phase A0: c2 transpose into smem, duplicated per value ----
    for (int i = t; i < 6400; i += 256) {
        int r = i >> 8, cz = i & 255;
        int cc = cz >> 4, z = cz & 15;
        float v = c2[cc * 400 + z * 25 + r];
        CsD[2 * i] = v;         // = r*512 + c*32 + z*2
        CsD[2 * i + 1] = v;
    }
    if (t == 0) {
        int ored = 0;
#pragma unroll
        for (int i = 0; i < 32; ++i) ored |= ids[2 * i + 1];
        sIds64 = (ored == 0) ? 1 : 0;
    }

    // ---- Phase A1: build this block's s rows (permuted layout) ----
    for (int pq = bid; pq < NROWS; pq += GRID) {
        int p = pq >> 5, q = pq & 31;
        __syncthreads();   // protect sA/sM reuse across iterations
        if (t < 128) {
            int x = t >> 4, b = t & 15;
            sA[t] = c0[x * 640 + p * 16 + b];
        }
        for (int i = t; i < 2048; i += 256) {
            int b = i >> 7, y = (i >> 4) & 7, cc = i & 15;
            sM[i] = c1[b * 4096 + y * 512 + q * 16 + cc];
        }
        __syncthreads();
        for (int o = t; o < 1024; o += 256) {
            int cc = o >> 6, xy = o & 63;
            int x = xy >> 3, y = xy & 7;
            float acc = 0.f;
#pragma unroll
            for (int b = 0; b < 16; ++b)
                acc += sA[x * 16 + b] * sM[b * 128 + y * 16 + cc];
            g_s[pq * 1024 + cc * 64 + ((xy & 7) << 3) + (xy >> 3)] = acc;
        }
    }

    // ---- grid-wide barrier (epoch tickets; replay-safe) ----
    __threadfence();
    __syncthreads();
    if (t == 0) {
        unsigned ticket = atomicAdd(&g_bar, 1u);
        unsigned target = (ticket / GRID + 1u) * GRID;
        while (atomicAdd(&g_bar, 0u) < target) __nanosleep(64);
    }
    __syncthreads();
    __threadfence();

    // ---- Phase B: gather ----
    int lane = t & 31, warp = t >> 5;
    int a = lane >> 2, zq = lane & 3;
    int ids64 = sIds64;

    for (int tok = bid * 8 + warp; tok < NTOK; tok += GRID * 8) {
        int id = ids64 ? __ldg(ids + 2 * tok) : __ldg(ids + tok);
        int p = id / 800;
        int rem = id - p * 800;
        int q = rem / 25;
        int r = rem - q * 25;

        // s row for this lane's a: pairs (m0,m1),(m2,m3),(m4,m5),(m6,m7) per c
        const float* sp = g_s + (p * 32 + q) * 1024 + a * 8;
        // duplicated c2t quad for this lane's z: 8 floats (4 dup-pairs) per c
        const float* cs = CsD + r * 512 + zq * 8;

        ull acc[4][4];   // [z within quad][m-pair]
#pragma unroll
        for (int zz = 0; zz < 4; ++zz)
#pragma unroll
            for (int mp = 0; mp < 4; ++mp) acc[zz][mp] = 0ull;

#pragma unroll
        for (int c = 0; c < 16; ++c) {
            ulonglong2 sv = *reinterpret_cast<const ulonglong2*>(sp + c * 64);
            ulonglong2 sw = *reinterpret_cast<const ulonglong2*>(sp + c * 64 + 4);
            ulonglong2 cd0 = *reinterpret_cast<const ulonglong2*>(cs + c * 32);
            ulonglong2 cd1 = *reinterpret_cast<const ulonglong2*>(cs + c * 32 + 4);

            asm("fma.rn.f32x2 %0,%1,%2,%0;" : "+l"(acc[0][0]) : "l"(sv.x), "l"(cd0.x));
            asm("fma.rn.f32x2 %0,%1,%2,%0;" : "+l"(acc[0][1]) : "l"(sv.y), "l"(cd0.x));
            asm("fma.rn.f32x2 %0,%1,%2,%0;" : "+l"(acc[0][2]) : "l"(sw.x), "l"(cd0.x));
            asm("fma.rn.f32x2 %0,%1,%2,%0;" : "+l"(acc[0][3]) : "l"(sw.y), "l"(cd0.x));
            asm("fma.rn.f32x2 %0,%1,%2,%0;" : "+l"(acc[1][0]) : "l"(sv.x), "l"(cd0.y));
            asm("fma.rn.f32x2 %0,%1,%2,%0;" : "+l"(acc[1][1]) : "l"(sv.y), "l"(cd0.y));
            asm("fma.rn.f32x2 %0,%1,%2,%0;" : "+l"(acc[1][2]) : "l"(sw.x), "l"(cd0.y));
            asm("fma.rn.f32x2 %0,%1,%2,%0;" : "+l"(acc[1][3]) : "l"(sw.y), "l"(cd0.y));
            asm("fma.rn.f32x2 %0,%1,%2,%0;" : "+l"(acc[2][0]) : "l"(sv.x), "l"(cd1.x));
            asm("fma.rn.f32x2 %0,%1,%2,%0;" : "+l"(acc[2][1]) : "l"(sv.y), "l"(cd1.x));
            asm("fma.rn.f32x2 %0,%1,%2,%0;" : "+l"(acc[2][2]) : "l"(sw.x), "l"(cd1.x));
            asm("fma.rn.f32x2 %0,%1,%2,%0;" : "+l"(acc[2][3]) : "l"(sw.y), "l"(cd1.x));
            asm("fma.rn.f32x2 %0,%1,%2,%0;" : "+l"(acc[3][0]) : "l"(sv.x), "l"(cd1.y));
            asm("fma.rn.f32x2 %0,%1,%2,%0;" : "+l"(acc[3][1]) : "l"(sv.y), "l"(cd1.y));
            asm("fma.rn.f32x2 %0,%1,%2,%0;" : "+l"(acc[3][2]) : "l"(sw.x), "l"(cd1.y));
            asm("fma.rn.f32x2 %0,%1,%2,%0;" : "+l"(acc[3][3]) : "l"(sw.y), "l"(cd1.y));
        }

        // transpose to z-major and store: rows m = 2mp, 2mp+1
        float* obase = out + (size_t)tok * 1024 + a * 16 + zq * 4;
#pragma unroll
        for (int mp = 0; mp < 4; ++mp) {
            float l0, h0, l1, h1, l2, h2, l3, h3;
            asm("mov.b64 {%0,%1},%2;" : "=f"(l0), "=f"(h0) : "l"(acc[0][mp]));
            asm("mov.b64 {%0,%1},%2;" : "=f"(l1), "=f"(h1) : "l"(acc[1][mp]));
            asm("mov.b64 {%0,%1},%2;" : "=f"(l2), "=f"(h2) : "l"(acc[2][mp]));
            asm("mov.b64 {%0,%1},%2;" : "=f"(l3), "=f"(h3) : "l"(acc[3][mp]));
            *reinterpret_cast<float4*>(obase + (2 * mp) * 128) =
                make_float4(l0, l1, l2, l3);
            *reinterpret_cast<float4*>(obase + (2 * mp + 1) * 128) =
                make_float4(h0, h1, h2, h3);
        }
    }
}

// ---------------------------------------------------------------------------
extern "C" void kernel_launch(void* const* d_in, const int* in_sizes, int n_in,
                              void* d_out, int out_size) {
    const float* core0 = (const float*)d_in[0];
    const float* core1 = (const float*)d_in[1];
    const float* core2 = (const float*)d_in[2];
    const int*   ids   = (const int*)d_in[3];
    float* out = (float*)d_out;

    tt_fused<<<GRID, 256>>>(core0, core1, core2, ids, out);
}